// round 7
// baseline (speedup 1.0000x reference)
#include <cuda_runtime.h>
#include <math.h>
#include <stdint.h>
#include <string.h>

#define PI_F 3.14159265358979323846f
#define RCUTF 5.0f
#define NT 10
#define WARPS 8
#define PERMCAP 66400
#define PCAP 50048
#define MMAX 2176

// ============================================================================
// Host-side exact replication of numpy RandomState(seed).standard_normal(...)
// ============================================================================
struct MT19937 {
    uint32_t mt[624];
    int mti;
    void seed(uint32_t s) {
        mt[0] = s;
        for (int i = 1; i < 624; i++)
            mt[i] = 1812433253u * (mt[i-1] ^ (mt[i-1] >> 30)) + (uint32_t)i;
        mti = 624;
    }
    uint32_t next() {
        if (mti >= 624) {
            for (int i = 0; i < 624; i++) {
                uint32_t y = (mt[i] & 0x80000000u) | (mt[(i+1) % 624] & 0x7fffffffu);
                mt[i] = mt[(i+397) % 624] ^ (y >> 1) ^ ((y & 1u) ? 2567483615u : 0u);
            }
            mti = 0;
        }
        uint32_t y = mt[mti++];
        y ^= y >> 11;
        y ^= (y << 7)  & 2636928640u;
        y ^= (y << 15) & 4022730752u;
        y ^= y >> 18;
        return y;
    }
    double rdouble() {
        uint32_t a = next() >> 5, b = next() >> 6;
        return (a * 67108864.0 + b) / 9007199254740992.0;
    }
};
struct GaussGen {
    MT19937 mt;
    bool has;
    double cached;
    void init(uint32_t s) { mt.seed(s); has = false; cached = 0.0; }
    double next() {
        if (has) { has = false; return cached; }
        double x1, x2, r2;
        do {
            x1 = 2.0 * mt.rdouble() - 1.0;
            x2 = 2.0 * mt.rdouble() - 1.0;
            r2 = x1 * x1 + x2 * x2;
        } while (r2 >= 1.0 || r2 == 0.0);
        double f = sqrt(-2.0 * log(r2) / r2);
        cached = f * x1; has = true;
        return f * x2;
    }
};

struct CGParam { float v[966]; };

static void fill_cg(float* out) {
    int off = 0;
    for (int l1 = 0; l1 < 3; l1++)
        for (int l2 = 0; l2 <= l1; l2++)
            for (int l3 = l1 - l2; l3 <= l1 + l2; l3++) {
                GaussGen g; g.init((uint32_t)(1000 + l1*100 + l2*10 + l3));
                int cnt = (2*l1+1) * (2*l2+1) * (2*l3+1);
                for (int q = 0; q < cnt; q++)
                    out[off++] = (float)g.next();
            }
}

// ============================================================================
// Compile-time index tables
// ============================================================================
struct Tables {
    unsigned char tri_x[21], tri_y[21];
    unsigned char et_combo[124], et_k[124], et_xy[124];
    unsigned char h_xy[36], h_l3[36];
    short cgoff[3][3][5];
    unsigned char om_xy[196], om_l1[196], om_l2[196], om_mn[196];
    short ds_t[196];
    unsigned char ds_xy[196], ds_klo[196], ds_len[196];
    short ds_off[196];
    int n_et, n_combo, m_total;
};

constexpr int trif(int x, int y) {
    int lo = x < y ? x : y, hi = x < y ? y : x;
    return hi * (hi + 1) / 2 + lo;
}

constexpr Tables makeTables() {
    Tables t{};
    for (int x = 0; x < 6; x++)
        for (int y = x; y < 6; y++) {
            t.tri_x[trif(x,y)] = (unsigned char)x;
            t.tri_y[trif(x,y)] = (unsigned char)y;
        }
    const int base[3] = {0, 3, 5};
    const int adim[3] = {3, 2, 1};
    {
        int off = 0;
        for (int l1 = 0; l1 < 3; l1++)
            for (int l2 = 0; l2 <= l1; l2++)
                for (int l3 = l1 - l2; l3 <= l1 + l2; l3++) {
                    t.cgoff[l1][l2][l3] = (short)off;
                    off += (2*l1+1) * (2*l2+1) * (2*l3+1);
                }
    }
    {
        bool seenE[21][25] = {};
        short comboId[21][5] = {};
        for (int a = 0; a < 21; a++)
            for (int b = 0; b < 5; b++) comboId[a][b] = -1;
        int ne = 0, nc = 0;
        for (int l1 = 0; l1 < 3; l1++)
            for (int l2 = 0; l2 <= l1; l2++)
                for (int xa = 0; xa < adim[l1]; xa++)
                    for (int xb = 0; xb < adim[l2]; xb++) {
                        int xy = trif(base[l1] + xa, base[l2] + xb);
                        for (int l3 = l1 - l2; l3 <= l1 + l2; l3++) {
                            if (comboId[xy][l3] < 0) {
                                comboId[xy][l3] = (short)nc;
                                t.h_xy[nc] = (unsigned char)xy;
                                t.h_l3[nc] = (unsigned char)l3;
                                nc++;
                            }
                            for (int ap = 0; ap < 2*l3 + 1; ap++) {
                                int k = l3*l3 + ap;
                                if (!seenE[xy][k]) {
                                    seenE[xy][k] = true;
                                    t.et_combo[ne] = (unsigned char)comboId[xy][l3];
                                    t.et_k[ne]  = (unsigned char)k;
                                    t.et_xy[ne] = (unsigned char)xy;
                                    ne++;
                                }
                            }
                        }
                    }
        t.n_et = ne;    // 121
        t.n_combo = nc; // 35
    }
    for (int r = 0; r < 14; r++)
        for (int c = 0; c < 14; c++) {
            int lr = r < 3 ? 0 : (r < 9 ? 1 : 2);
            int xr = r - (lr == 0 ? 0 : (lr == 1 ? 3 : 9));
            int lc = c < 3 ? 0 : (c < 9 ? 1 : 2);
            int xc = c - (lc == 0 ? 0 : (lc == 1 ? 3 : 9));
            int l1 = 0, l2 = 0, X = 0, Y = 0;
            if (lr >= lc) { l1 = lr; l2 = lc; X = xr; Y = xc; }
            else          { l1 = lc; l2 = lr; X = xc; Y = xr; }
            int N = 2*l2 + 1, A = adim[l1], B = adim[l2];
            int flat = X * (N * B) + Y;
            int b = flat % B; int tmp = flat / B;
            int a = tmp % A; tmp /= A;
            int n2 = tmp % N; int m = tmp / N;
            int idx = r * 14 + c;
            t.om_xy[idx] = (unsigned char)trif(base[l1] + a, base[l2] + b);
            t.om_l1[idx] = (unsigned char)l1;
            t.om_l2[idx] = (unsigned char)l2;
            t.om_mn[idx] = (unsigned char)(m * N + n2);
        }
    {
        const int lens[6] = {25, 15, 9, 5, 3, 1};
        int n = 0;
        int moff = 0;
        for (int li = 0; li < 6; li++)
            for (int tt = 0; tt < 196; tt++) {
                int l1 = t.om_l1[tt], l2 = t.om_l2[tt];
                int klo = (l1 - l2) * (l1 - l2);
                int khi = (l1 + l2 + 1) * (l1 + l2 + 1);
                if (khi - klo == lens[li]) {
                    t.ds_t[n] = (short)tt;
                    t.ds_xy[n] = t.om_xy[tt];
                    t.ds_klo[n] = (unsigned char)klo;
                    t.ds_len[n] = (unsigned char)(khi - klo);
                    t.ds_off[n] = (short)moff;
                    moff += khi - klo;
                    n++;
                }
            }
        t.m_total = moff; // 2116
    }
    return t;
}

__constant__ Tables TBc = makeTables();

// Global scratch
__device__ float Hg[100 * 35 * 16];
__device__ float Mg[MMAX];
__device__ int cntg[100];
__device__ int fillg[100];
__device__ int permg[PERMCAP];
__device__ unsigned char tpg[PCAP];

// ============================================================================
// H precompute
// ============================================================================
__global__ void h_kernel(const float* __restrict__ weight,
                         const float* __restrict__ s_col,
                         const float* __restrict__ p_col,
                         const float* __restrict__ d_col)
{
    __shared__ float coll[96];
    int tid = threadIdx.x;
    if (tid < 96) {
        float v;
        if (tid < 48)      v = s_col[tid];
        else if (tid < 80) v = p_col[tid - 48];
        else               v = d_col[tid - 80];
        coll[tid] = v;
    }
    __syncthreads();
    if (tid >= 560) return;
    int tp = blockIdx.x;
    int t1 = tp / NT, t2 = tp % NT;
    int combo = tid >> 4, c = tid & 15;
    int xy = TBc.h_xy[combo], l3 = TBc.h_l3[combo];
    int x = TBc.tri_x[xy], y = TBc.tri_y[xy];
    const float* w1 = weight + (size_t)(t1 * NT + t2) * 1280 + l3 * 256;
    const float* w2 = weight + (size_t)(t2 * NT + t1) * 1280 + l3 * 256;
    float acc = 0.f;
    #pragma unroll
    for (int b = 0; b < 16; b++)
        acc += coll[x * 16 + b] * coll[y * 16 + b] * (w1[b * 16 + c] + w2[b * 16 + c]);
    Hg[(tp * 35 + combo) * 16 + c] = acc;
}

// ============================================================================
// Packed M build (one block)
// ============================================================================
__global__ void m_kernel(const __grid_constant__ CGParam cgp) {
    int e = threadIdx.x;
    if (e >= 196) return;
    int t  = TBc.ds_t[e];
    int l1 = TBc.om_l1[t], l2 = TBc.om_l2[t], mn = TBc.om_mn[t];
    int klo = TBc.ds_klo[e], len = TBc.ds_len[e], off = TBc.ds_off[e];
    for (int q = 0; q < len; q++) {
        int k = klo + q;
        int l3 = (k < 1) ? 0 : (k < 4) ? 1 : (k < 9) ? 2 : (k < 16) ? 3 : 4;
        int ap = k - l3 * l3;
        Mg[off + q] = cgp.v[TBc.cgoff[l1][l2][l3] + mn * (2 * l3 + 1) + ap];
    }
}

// ============================================================================
// Binning
// ============================================================================
__global__ void init_kernel() {
    int idx = blockIdx.x * blockDim.x + threadIdx.x;
    if (idx < PERMCAP) permg[idx] = -1;
    if (idx < 100) cntg[idx] = 0;
}

__global__ void count_kernel(const int* __restrict__ Z,
                             const int* __restrict__ pairs,
                             const int* __restrict__ aidx, int Pn) {
    int p = blockIdx.x * blockDim.x + threadIdx.x;
    if (p >= Pn) return;
    int ai = aidx[p];
    int t1 = Z[pairs[2 * ai]];
    int t2 = Z[pairs[2 * ai + 1]];
    int tp = t1 * NT + t2;
    tpg[p] = (unsigned char)tp;
    atomicAdd(&cntg[tp], 1);
}

__global__ void scan_kernel() {
    __shared__ int c_s[100];
    int tid = threadIdx.x;
    if (tid < 100) c_s[tid] = cntg[tid];
    __syncthreads();
    if (tid == 0) {
        int run = 0;
        for (int b = 0; b < 100; b++) {
            int c = c_s[b];
            c_s[b] = run;
            run += (c + 7) & ~7;
        }
    }
    __syncthreads();
    if (tid < 100) fillg[tid] = c_s[tid];
}

__global__ void scatter_kernel(int Pn) {
    int p = blockIdx.x * blockDim.x + threadIdx.x;
    if (p >= Pn) return;
    int pos = atomicAdd(&fillg[tpg[p]], 1);
    permg[pos] = p;
}

// ============================================================================
// Main kernel: one warp per binned pair slot; CTA-uniform type-pair
// Dyn smem/warp (floats): rbf[0,32) gsh[32,112) cinS[112,612) (25 x stride20)
//                         Ew[612,1137) (21 x 25)   WSLOT=1140 (16B aligned)
// ============================================================================
#define WSLOT 1140

__global__ void __launch_bounds__(256) op_kernel(
    const float* __restrict__ c0, const float* __restrict__ c1,
    const float* __restrict__ c2, const float* __restrict__ c3,
    const float* __restrict__ c4,
    const float* __restrict__ Rpos, const float* __restrict__ w_rad,
    const int* __restrict__ pairs,
    float* __restrict__ out)
{
    __shared__ __align__(16) float Hs[35 * 20];      // stride 20 (80B rows)
    __shared__ __align__(16) float Mv[MMAX];
    __shared__ unsigned char etc_s[121], etk_s[121], etxy_s[121];
    __shared__ short dst_s[196], dsoff_s[196];
    __shared__ unsigned char dsxy_s[196], dsklo_s[196], dslen_s[196];
    __shared__ int ctaTp;
    extern __shared__ __align__(16) float dyn[];

    int tid = threadIdx.x, w = tid >> 5, lane = tid & 31;
    int base = blockIdx.x * WARPS;

    if (tid == 0) {
        int pe0 = permg[base];
        ctaTp = (pe0 >= 0) ? (int)tpg[pe0] : -1;
    }
    for (int idx = tid; idx < TBc.m_total; idx += 256) Mv[idx] = Mg[idx];
    if (tid < 121) {
        etc_s[tid]  = TBc.et_combo[tid];
        etk_s[tid]  = TBc.et_k[tid];
        etxy_s[tid] = TBc.et_xy[tid];
    }
    if (tid < 196) {
        dst_s[tid]   = TBc.ds_t[tid];
        dsoff_s[tid] = TBc.ds_off[tid];
        dsxy_s[tid]  = TBc.ds_xy[tid];
        dsklo_s[tid] = TBc.ds_klo[tid];
        dslen_s[tid] = TBc.ds_len[tid];
    }
    __syncthreads();
    int tpc = ctaTp;
    if (tpc < 0) return;
    {
        const float* Hsrc = Hg + (size_t)tpc * 560;
        for (int idx = tid; idx < 560; idx += 256) {
            int combo = idx >> 4, c = idx & 15;
            Hs[combo * 20 + c] = Hsrc[idx];
        }
    }
    __syncthreads();

    int pe = permg[base + w];
    if (pe < 0) return;

    float* Wp   = dyn + w * WSLOT;
    float* rbf  = Wp;
    float* gsh  = Wp + 32;
    float* cinS = Wp + 112;      // stride 20
    float* Ew   = Wp + 612;      // stride 25

    int i = pairs[2 * pe], j = pairs[2 * pe + 1];

    float dx = Rpos[3*i+0] - Rpos[3*j+0];
    float dy = Rpos[3*i+1] - Rpos[3*j+1];
    float dz = Rpos[3*i+2] - Rpos[3*j+2];
    float d  = sqrtf(dx*dx + dy*dy + dz*dz);
    float env = (d < RCUTF) ? 0.5f * (cosf(PI_F * d / RCUTF) + 1.0f) : 0.0f;
    rbf[lane] = sinf((float)(lane + 1) * PI_F * d / RCUTF) * env;
    __syncwarp();

    int f = lane & 15, h = lane >> 4;

    // ---- Phase A: g[l][f] = sum_k rbf[k] * w_rad[l][k][f] (w_rad via L1) ----
    #pragma unroll
    for (int li = 0; li < 3; li++) {
        if (!h || li < 2) {
            int l = h ? li + 3 : li;
            const float* wl = w_rad + l * 512 + f;
            float a0 = 0.f, a1 = 0.f, a2 = 0.f, a3 = 0.f;
            #pragma unroll
            for (int q = 0; q < 8; q++) {
                a0 = fmaf(rbf[4*q+0], __ldg(wl + (4*q+0)*16), a0);
                a1 = fmaf(rbf[4*q+1], __ldg(wl + (4*q+1)*16), a1);
                a2 = fmaf(rbf[4*q+2], __ldg(wl + (4*q+2)*16), a2);
                a3 = fmaf(rbf[4*q+3], __ldg(wl + (4*q+3)*16), a3);
            }
            gsh[l * 16 + f] = (a0 + a1) + (a2 + a3);
        }
    }
    __syncwarp();

    // ---- Stage cin[k=l^2+m][c] = g[l][c]*(ci+cj), stride 20 ----
    {
        const float* clp[5] = {c0, c1, c2, c3, c4};
        #pragma unroll
        for (int l = 0; l < 5; l++) {
            const int nm = 2 * l + 1;
            const float* ci = clp[l] + (size_t)i * 16 * nm;
            const float* cj = clp[l] + (size_t)j * 16 * nm;
            for (int idx = lane; idx < 16 * nm; idx += 32) {
                int c = idx / nm, m = idx - c * nm;
                cinS[(l * l + m) * 20 + c] = gsh[l * 16 + c] * (ci[idx] + cj[idx]);
            }
        }
    }
    __syncwarp();

    // ---- Phase C': E[xy][k] = sum_c Hs[combo][c] * cin[k][c] (vectorized) ----
    for (int e = lane; e < 121; e += 32) {
        int combo = etc_s[e], k = etk_s[e], xy = etxy_s[e];
        const float4* Hr = (const float4*)(Hs + combo * 20);
        const float4* cr = (const float4*)(cinS + k * 20);
        float4 h0 = Hr[0], h1 = Hr[1], h2 = Hr[2], h3 = Hr[3];
        float4 q0 = cr[0], q1 = cr[1], q2 = cr[2], q3 = cr[3];
        float acc = 0.f;
        acc = fmaf(h0.x, q0.x, acc); acc = fmaf(h0.y, q0.y, acc);
        acc = fmaf(h0.z, q0.z, acc); acc = fmaf(h0.w, q0.w, acc);
        acc = fmaf(h1.x, q1.x, acc); acc = fmaf(h1.y, q1.y, acc);
        acc = fmaf(h1.z, q1.z, acc); acc = fmaf(h1.w, q1.w, acc);
        acc = fmaf(h2.x, q2.x, acc); acc = fmaf(h2.y, q2.y, acc);
        acc = fmaf(h2.z, q2.z, acc); acc = fmaf(h2.w, q2.w, acc);
        acc = fmaf(h3.x, q3.x, acc); acc = fmaf(h3.y, q3.y, acc);
        acc = fmaf(h3.z, q3.z, acc); acc = fmaf(h3.w, q3.w, acc);
        Ew[xy * 25 + k] = acc;
    }
    __syncwarp();

    // ---- Phase D: out[t] = sum_q Mv[off+q] * E[xy][klo+q] ----
    float* op = out + (size_t)pe * 196;
    for (int e = lane; e < 196; e += 32) {
        int t = dst_s[e];
        const float* Mr = Mv + dsoff_s[e];
        const float* Er = Ew + dsxy_s[e] * 25 + dsklo_s[e];
        int len = dslen_s[e];
        float acc = 0.f;
        for (int q = 0; q < len; q++)
            acc = fmaf(Mr[q], Er[q], acc);
        op[t] = acc;
    }
}

// ============================================================================
// Launch
// ============================================================================
extern "C" void kernel_launch(void* const* d_in, const int* in_sizes, int n_in,
                              void* d_out, int out_size) {
    const float* c0    = (const float*)d_in[0];
    const float* c1    = (const float*)d_in[1];
    const float* c2    = (const float*)d_in[2];
    const float* c3    = (const float*)d_in[3];
    const float* c4    = (const float*)d_in[4];
    const float* Rpos  = (const float*)d_in[5];
    const float* w_rad = (const float*)d_in[6];
    const float* wgt   = (const float*)d_in[7];
    const float* s_col = (const float*)d_in[8];
    const float* p_col = (const float*)d_in[9];
    const float* d_col = (const float*)d_in[10];
    const int*   Z     = (const int*)d_in[11];
    const int*   pairs = (const int*)d_in[12];
    const int*   aidx  = (const int*)d_in[13];
    float* out = (float*)d_out;

    int Pn = in_sizes[13];

    CGParam cg;
    fill_cg(cg.v);

    h_kernel<<<100, 576>>>(wgt, s_col, p_col, d_col);
    m_kernel<<<1, 256>>>(cg);
    init_kernel<<<(PERMCAP + 255) / 256, 256>>>();
    count_kernel<<<(Pn + 255) / 256, 256>>>(Z, pairs, aidx, Pn);
    scan_kernel<<<1, 128>>>();
    scatter_kernel<<<(Pn + 255) / 256, 256>>>(Pn);

    size_t shmem = (size_t)WARPS * WSLOT * sizeof(float);
    cudaFuncSetAttribute(op_kernel, cudaFuncAttributeMaxDynamicSharedMemorySize, (int)shmem);
    int gridMain = (Pn + 700 + 7) / 8;
    op_kernel<<<gridMain, 256, shmem>>>(c0, c1, c2, c3, c4, Rpos, w_rad,
                                        pairs, out);
}

// round 8
// speedup vs baseline: 1.1369x; 1.1369x over previous
#include <cuda_runtime.h>
#include <math.h>
#include <stdint.h>
#include <string.h>

#define PI_F 3.14159265358979323846f
#define RCUTF 5.0f
#define NT 10
#define WARPS 8
#define PERMCAP 50704
#define PCAP 50048
#define MMAX 2176

// ============================================================================
// Host-side exact replication of numpy RandomState(seed).standard_normal(...)
// ============================================================================
struct MT19937 {
    uint32_t mt[624];
    int mti;
    void seed(uint32_t s) {
        mt[0] = s;
        for (int i = 1; i < 624; i++)
            mt[i] = 1812433253u * (mt[i-1] ^ (mt[i-1] >> 30)) + (uint32_t)i;
        mti = 624;
    }
    uint32_t next() {
        if (mti >= 624) {
            for (int i = 0; i < 624; i++) {
                uint32_t y = (mt[i] & 0x80000000u) | (mt[(i+1) % 624] & 0x7fffffffu);
                mt[i] = mt[(i+397) % 624] ^ (y >> 1) ^ ((y & 1u) ? 2567483615u : 0u);
            }
            mti = 0;
        }
        uint32_t y = mt[mti++];
        y ^= y >> 11;
        y ^= (y << 7)  & 2636928640u;
        y ^= (y << 15) & 4022730752u;
        y ^= y >> 18;
        return y;
    }
    double rdouble() {
        uint32_t a = next() >> 5, b = next() >> 6;
        return (a * 67108864.0 + b) / 9007199254740992.0;
    }
};
struct GaussGen {
    MT19937 mt;
    bool has;
    double cached;
    void init(uint32_t s) { mt.seed(s); has = false; cached = 0.0; }
    double next() {
        if (has) { has = false; return cached; }
        double x1, x2, r2;
        do {
            x1 = 2.0 * mt.rdouble() - 1.0;
            x2 = 2.0 * mt.rdouble() - 1.0;
            r2 = x1 * x1 + x2 * x2;
        } while (r2 >= 1.0 || r2 == 0.0);
        double f = sqrt(-2.0 * log(r2) / r2);
        cached = f * x1; has = true;
        return f * x2;
    }
};

struct CGParam { float v[966]; };

static void fill_cg(float* out) {
    int off = 0;
    for (int l1 = 0; l1 < 3; l1++)
        for (int l2 = 0; l2 <= l1; l2++)
            for (int l3 = l1 - l2; l3 <= l1 + l2; l3++) {
                GaussGen g; g.init((uint32_t)(1000 + l1*100 + l2*10 + l3));
                int cnt = (2*l1+1) * (2*l2+1) * (2*l3+1);
                for (int q = 0; q < cnt; q++)
                    out[off++] = (float)g.next();
            }
}

// ============================================================================
// Compile-time index tables
// ============================================================================
struct Tables {
    unsigned char tri_x[21], tri_y[21];
    unsigned char et_combo[124], et_k[124], et_xy[124];
    unsigned char h_xy[36], h_l3[36];
    short cgoff[3][3][5];
    unsigned char om_xy[196], om_l1[196], om_l2[196], om_mn[196];
    short ds_t[196];
    unsigned char ds_xy[196], ds_klo[196], ds_len[196];
    short ds_off[196];
    int n_et, n_combo, m_total;
};

constexpr int trif(int x, int y) {
    int lo = x < y ? x : y, hi = x < y ? y : x;
    return hi * (hi + 1) / 2 + lo;
}

constexpr Tables makeTables() {
    Tables t{};
    for (int x = 0; x < 6; x++)
        for (int y = x; y < 6; y++) {
            t.tri_x[trif(x,y)] = (unsigned char)x;
            t.tri_y[trif(x,y)] = (unsigned char)y;
        }
    const int base[3] = {0, 3, 5};
    const int adim[3] = {3, 2, 1};
    {
        int off = 0;
        for (int l1 = 0; l1 < 3; l1++)
            for (int l2 = 0; l2 <= l1; l2++)
                for (int l3 = l1 - l2; l3 <= l1 + l2; l3++) {
                    t.cgoff[l1][l2][l3] = (short)off;
                    off += (2*l1+1) * (2*l2+1) * (2*l3+1);
                }
    }
    {
        bool seenE[21][25] = {};
        short comboId[21][5] = {};
        for (int a = 0; a < 21; a++)
            for (int b = 0; b < 5; b++) comboId[a][b] = -1;
        int ne = 0, nc = 0;
        for (int l1 = 0; l1 < 3; l1++)
            for (int l2 = 0; l2 <= l1; l2++)
                for (int xa = 0; xa < adim[l1]; xa++)
                    for (int xb = 0; xb < adim[l2]; xb++) {
                        int xy = trif(base[l1] + xa, base[l2] + xb);
                        for (int l3 = l1 - l2; l3 <= l1 + l2; l3++) {
                            if (comboId[xy][l3] < 0) {
                                comboId[xy][l3] = (short)nc;
                                t.h_xy[nc] = (unsigned char)xy;
                                t.h_l3[nc] = (unsigned char)l3;
                                nc++;
                            }
                            for (int ap = 0; ap < 2*l3 + 1; ap++) {
                                int k = l3*l3 + ap;
                                if (!seenE[xy][k]) {
                                    seenE[xy][k] = true;
                                    t.et_combo[ne] = (unsigned char)comboId[xy][l3];
                                    t.et_k[ne]  = (unsigned char)k;
                                    t.et_xy[ne] = (unsigned char)xy;
                                    ne++;
                                }
                            }
                        }
                    }
        t.n_et = ne;    // 121
        t.n_combo = nc; // 35
    }
    for (int r = 0; r < 14; r++)
        for (int c = 0; c < 14; c++) {
            int lr = r < 3 ? 0 : (r < 9 ? 1 : 2);
            int xr = r - (lr == 0 ? 0 : (lr == 1 ? 3 : 9));
            int lc = c < 3 ? 0 : (c < 9 ? 1 : 2);
            int xc = c - (lc == 0 ? 0 : (lc == 1 ? 3 : 9));
            int l1 = 0, l2 = 0, X = 0, Y = 0;
            if (lr >= lc) { l1 = lr; l2 = lc; X = xr; Y = xc; }
            else          { l1 = lc; l2 = lr; X = xc; Y = xr; }
            int N = 2*l2 + 1, A = adim[l1], B = adim[l2];
            int flat = X * (N * B) + Y;
            int b = flat % B; int tmp = flat / B;
            int a = tmp % A; tmp /= A;
            int n2 = tmp % N; int m = tmp / N;
            int idx = r * 14 + c;
            t.om_xy[idx] = (unsigned char)trif(base[l1] + a, base[l2] + b);
            t.om_l1[idx] = (unsigned char)l1;
            t.om_l2[idx] = (unsigned char)l2;
            t.om_mn[idx] = (unsigned char)(m * N + n2);
        }
    {
        const int lens[6] = {25, 15, 9, 5, 3, 1};
        int n = 0;
        int moff = 0;
        for (int li = 0; li < 6; li++)
            for (int tt = 0; tt < 196; tt++) {
                int l1 = t.om_l1[tt], l2 = t.om_l2[tt];
                int klo = (l1 - l2) * (l1 - l2);
                int khi = (l1 + l2 + 1) * (l1 + l2 + 1);
                if (khi - klo == lens[li]) {
                    t.ds_t[n] = (short)tt;
                    t.ds_xy[n] = t.om_xy[tt];
                    t.ds_klo[n] = (unsigned char)klo;
                    t.ds_len[n] = (unsigned char)(khi - klo);
                    t.ds_off[n] = (short)moff;
                    moff += khi - klo;
                    n++;
                }
            }
        t.m_total = moff; // 2116
    }
    return t;
}

__constant__ Tables TBc = makeTables();

// Global scratch
__device__ float Hg[100 * 35 * 16];
__device__ float Mg[MMAX];
__device__ int cntg[100];
__device__ int fillg[100];
__device__ int permg[PERMCAP];
__device__ unsigned char tpg[PCAP];

// ============================================================================
// Setup kernel (grid=100, block=576):
//  - H[tp][combo][c] for block tp
//  - zero cntg
//  - init permg
//  - block 0 additionally builds packed M
// ============================================================================
__global__ void h_kernel(const float* __restrict__ weight,
                         const float* __restrict__ s_col,
                         const float* __restrict__ p_col,
                         const float* __restrict__ d_col,
                         const __grid_constant__ CGParam cgp)
{
    __shared__ float coll[96];
    int tid = threadIdx.x;
    if (tid < 96) {
        float v;
        if (tid < 48)      v = s_col[tid];
        else if (tid < 80) v = p_col[tid - 48];
        else               v = d_col[tid - 80];
        coll[tid] = v;
    }
    if (tid == 0) cntg[blockIdx.x] = 0;
    {
        int gtid = blockIdx.x * 576 + tid;
        for (int idx = gtid; idx < PERMCAP; idx += 100 * 576)
            permg[idx] = -1;
    }
    if (blockIdx.x == 0 && tid < 196) {
        int e = tid;
        int t  = TBc.ds_t[e];
        int l1 = TBc.om_l1[t], l2 = TBc.om_l2[t], mn = TBc.om_mn[t];
        int klo = TBc.ds_klo[e], len = TBc.ds_len[e], off = TBc.ds_off[e];
        for (int q = 0; q < len; q++) {
            int k = klo + q;
            int l3 = (k < 1) ? 0 : (k < 4) ? 1 : (k < 9) ? 2 : (k < 16) ? 3 : 4;
            int ap = k - l3 * l3;
            Mg[off + q] = cgp.v[TBc.cgoff[l1][l2][l3] + mn * (2 * l3 + 1) + ap];
        }
    }
    __syncthreads();
    if (tid >= 560) return;
    int tp = blockIdx.x;
    int t1 = tp / NT, t2 = tp % NT;
    int combo = tid >> 4, c = tid & 15;
    int xy = TBc.h_xy[combo], l3 = TBc.h_l3[combo];
    int x = TBc.tri_x[xy], y = TBc.tri_y[xy];
    const float* w1 = weight + (size_t)(t1 * NT + t2) * 1280 + l3 * 256;
    const float* w2 = weight + (size_t)(t2 * NT + t1) * 1280 + l3 * 256;
    float acc = 0.f;
    #pragma unroll
    for (int b = 0; b < 16; b++)
        acc += coll[x * 16 + b] * coll[y * 16 + b] * (w1[b * 16 + c] + w2[b * 16 + c]);
    Hg[(tp * 35 + combo) * 16 + c] = acc;
}

// ============================================================================
// Binning: smem-aggregated count and scatter
// ============================================================================
__global__ void count_kernel(const int* __restrict__ Z,
                             const int* __restrict__ pairs,
                             const int* __restrict__ aidx, int Pn) {
    __shared__ int loc[100];
    int tid = threadIdx.x;
    if (tid < 100) loc[tid] = 0;
    __syncthreads();
    int p = blockIdx.x * blockDim.x + tid;
    if (p < Pn) {
        int ai = aidx[p];
        int t1 = Z[pairs[2 * ai]];
        int t2 = Z[pairs[2 * ai + 1]];
        int tp = t1 * NT + t2;
        tpg[p] = (unsigned char)tp;
        atomicAdd(&loc[tp], 1);
    }
    __syncthreads();
    if (tid < 100 && loc[tid] > 0) atomicAdd(&cntg[tid], loc[tid]);
}

__global__ void scan_kernel() {
    __shared__ int c_s[100];
    int tid = threadIdx.x;
    if (tid < 100) c_s[tid] = cntg[tid];
    __syncthreads();
    if (tid == 0) {
        int run = 0;
        for (int b = 0; b < 100; b++) {
            int c = c_s[b];
            c_s[b] = run;
            run += (c + 7) & ~7;
        }
    }
    __syncthreads();
    if (tid < 100) fillg[tid] = c_s[tid];
}

__global__ void scatter_kernel(int Pn) {
    __shared__ int loc[100];
    __shared__ int base_s[100];
    int tid = threadIdx.x;
    if (tid < 100) loc[tid] = 0;
    __syncthreads();
    int p = blockIdx.x * blockDim.x + tid;
    int tp = -1, rank = 0;
    if (p < Pn) {
        tp = (int)tpg[p];
        rank = atomicAdd(&loc[tp], 1);
    }
    __syncthreads();
    if (tid < 100)
        base_s[tid] = (loc[tid] > 0) ? atomicAdd(&fillg[tid], loc[tid]) : 0;
    __syncthreads();
    if (p < Pn)
        permg[base_s[tp] + rank] = p;
}

// ============================================================================
// Main kernel: one warp per binned pair slot; CTA-uniform type-pair
// Dyn smem/warp: rbf[0,32) gsh[32,112) cinS[112,537) (25x17) Ew[544,1069) (21x25)
// ============================================================================
#define WSLOT 1072

__global__ void __launch_bounds__(256) op_kernel(
    const float* __restrict__ c0, const float* __restrict__ c1,
    const float* __restrict__ c2, const float* __restrict__ c3,
    const float* __restrict__ c4,
    const float* __restrict__ Rpos, const float* __restrict__ w_rad,
    const int* __restrict__ pairs,
    float* __restrict__ out)
{
    __shared__ __align__(16) float Hs[35 * 17 + 5];
    __shared__ __align__(16) float Mv[MMAX];
    __shared__ unsigned char etc_s[121], etk_s[121], etxy_s[121];
    __shared__ short dst_s[196], dsoff_s[196];
    __shared__ unsigned char dsxy_s[196], dsklo_s[196], dslen_s[196];
    __shared__ int ctaTp;
    extern __shared__ __align__(16) float dyn[];

    int tid = threadIdx.x, w = tid >> 5, lane = tid & 31;
    int base = blockIdx.x * WARPS;

    if (tid == 0) {
        int pe0 = permg[base];
        ctaTp = (pe0 >= 0) ? (int)tpg[pe0] : -1;
    }
    for (int idx = tid; idx < TBc.m_total; idx += 256) Mv[idx] = Mg[idx];
    if (tid < 121) {
        etc_s[tid]  = TBc.et_combo[tid];
        etk_s[tid]  = TBc.et_k[tid];
        etxy_s[tid] = TBc.et_xy[tid];
    }
    if (tid < 196) {
        dst_s[tid]   = TBc.ds_t[tid];
        dsoff_s[tid] = TBc.ds_off[tid];
        dsxy_s[tid]  = TBc.ds_xy[tid];
        dsklo_s[tid] = TBc.ds_klo[tid];
        dslen_s[tid] = TBc.ds_len[tid];
    }
    __syncthreads();
    int tpc = ctaTp;
    if (tpc < 0) return;
    {
        const float* Hsrc = Hg + (size_t)tpc * 560;
        for (int idx = tid; idx < 560; idx += 256) {
            int combo = idx >> 4, c = idx & 15;
            Hs[combo * 17 + c] = Hsrc[idx];
        }
    }
    __syncthreads();

    int pe = permg[base + w];
    if (pe < 0) return;

    float* Wp   = dyn + w * WSLOT;
    float* rbf  = Wp;
    float* gsh  = Wp + 32;
    float* cinS = Wp + 112;
    float* Ew   = Wp + 544;

    int i = pairs[2 * pe], j = pairs[2 * pe + 1];

    float dx = Rpos[3*i+0] - Rpos[3*j+0];
    float dy = Rpos[3*i+1] - Rpos[3*j+1];
    float dz = Rpos[3*i+2] - Rpos[3*j+2];
    float d  = sqrtf(dx*dx + dy*dy + dz*dz);
    float env = (d < RCUTF) ? 0.5f * (cosf(PI_F * d / RCUTF) + 1.0f) : 0.0f;
    rbf[lane] = sinf((float)(lane + 1) * PI_F * d / RCUTF) * env;
    __syncwarp();

    int f = lane & 15, h = lane >> 4;

    // ---- Phase A: g[l][f] = sum_k rbf[k] * w_rad[l][k][f] (w_rad via L1) ----
    #pragma unroll
    for (int li = 0; li < 3; li++) {
        if (!h || li < 2) {
            int l = h ? li + 3 : li;
            const float* wl = w_rad + l * 512 + f;
            float a0 = 0.f, a1 = 0.f, a2 = 0.f, a3 = 0.f;
            #pragma unroll
            for (int q = 0; q < 8; q++) {
                a0 = fmaf(rbf[4*q+0], __ldg(wl + (4*q+0)*16), a0);
                a1 = fmaf(rbf[4*q+1], __ldg(wl + (4*q+1)*16), a1);
                a2 = fmaf(rbf[4*q+2], __ldg(wl + (4*q+2)*16), a2);
                a3 = fmaf(rbf[4*q+3], __ldg(wl + (4*q+3)*16), a3);
            }
            gsh[l * 16 + f] = (a0 + a1) + (a2 + a3);
        }
    }
    __syncwarp();

    // ---- Stage cin[k=l^2+m][c] = g[l][c]*(ci+cj), stride 17 ----
    {
        const float* clp[5] = {c0, c1, c2, c3, c4};
        #pragma unroll
        for (int l = 0; l < 5; l++) {
            const int nm = 2 * l + 1;
            const float* ci = clp[l] + (size_t)i * 16 * nm;
            const float* cj = clp[l] + (size_t)j * 16 * nm;
            for (int idx = lane; idx < 16 * nm; idx += 32) {
                int c = idx / nm, m = idx - c * nm;
                cinS[(l * l + m) * 17 + c] = gsh[l * 16 + c] * (ci[idx] + cj[idx]);
            }
        }
    }
    __syncwarp();

    // ---- Phase C': E[xy][k] = sum_c Hs[combo][c] * cin[k][c] ----
    for (int e = lane; e < 121; e += 32) {
        int combo = etc_s[e], k = etk_s[e], xy = etxy_s[e];
        const float* Hr = Hs + combo * 17;
        const float* cr = cinS + k * 17;
        float acc = 0.f;
        #pragma unroll
        for (int c = 0; c < 16; c++)
            acc = fmaf(Hr[c], cr[c], acc);
        Ew[xy * 25 + k] = acc;
    }
    __syncwarp();

    // ---- Phase D: out[t] = sum_q Mv[off+q] * E[xy][klo+q] ----
    float* op = out + (size_t)pe * 196;
    for (int e = lane; e < 196; e += 32) {
        int t = dst_s[e];
        const float* Mr = Mv + dsoff_s[e];
        const float* Er = Ew + dsxy_s[e] * 25 + dsklo_s[e];
        int len = dslen_s[e];
        float acc = 0.f;
        for (int q = 0; q < len; q++)
            acc = fmaf(Mr[q], Er[q], acc);
        op[t] = acc;
    }
}

// ============================================================================
// Launch
// ============================================================================
extern "C" void kernel_launch(void* const* d_in, const int* in_sizes, int n_in,
                              void* d_out, int out_size) {
    const float* c0    = (const float*)d_in[0];
    const float* c1    = (const float*)d_in[1];
    const float* c2    = (const float*)d_in[2];
    const float* c3    = (const float*)d_in[3];
    const float* c4    = (const float*)d_in[4];
    const float* Rpos  = (const float*)d_in[5];
    const float* w_rad = (const float*)d_in[6];
    const float* wgt   = (const float*)d_in[7];
    const float* s_col = (const float*)d_in[8];
    const float* p_col = (const float*)d_in[9];
    const float* d_col = (const float*)d_in[10];
    const int*   Z     = (const int*)d_in[11];
    const int*   pairs = (const int*)d_in[12];
    const int*   aidx  = (const int*)d_in[13];
    float* out = (float*)d_out;

    int Pn = in_sizes[13];

    CGParam cg;
    fill_cg(cg.v);

    h_kernel<<<100, 576>>>(wgt, s_col, p_col, d_col, cg);
    count_kernel<<<(Pn + 255) / 256, 256>>>(Z, pairs, aidx, Pn);
    scan_kernel<<<1, 128>>>();
    scatter_kernel<<<(Pn + 255) / 256, 256>>>(Pn);

    size_t shmem = (size_t)WARPS * WSLOT * sizeof(float);
    cudaFuncSetAttribute(op_kernel, cudaFuncAttributeMaxDynamicSharedMemorySize, (int)shmem);
    int gridMain = (Pn + 700 + 7) / 8;
    op_kernel<<<gridMain, 256, shmem>>>(c0, c1, c2, c3, c4, Rpos, w_rad,
                                        pairs, out);
}